// round 17
// baseline (speedup 1.0000x reference)
#include <cuda_runtime.h>
#include <math.h>
#include <stdint.h>

// Problem constants
#define HD   4096
#define IS   2048
#define NE   16
#define NK   4
#define SIW  2048
#define TMAX 4096

// GEMM tile: CTA 128(M) x 256(B-rows), 8 warps (2M x 4N), warp tile 64x64, K-chunk 32
#define BM   128
#define BNR  256                             // B rows staged in smem per CTA
#define BKT  32
#define LSTR 36                              // padded row stride (floats)
#define SM_A_FLOATS (BM * LSTR)              // 4608
#define SM_B_FLOATS (BNR * LSTR)             // 9216
#define SM_STAGE    (SM_A_FLOATS + SM_B_FLOATS)   // 13824 floats
#define STAGE_BYTES (SM_STAGE * 4)           // 55296
#define DSMEM_BYTES (2 * STAGE_BYTES)        // 110592

// ---------------- static device scratch ----------------
__device__ int   d_cnt[NE];
__device__ int   d_tok[NE * TMAX];
__device__ float d_wgt[NE * TMAX];
__device__ float d_bufZ[(size_t)NE * TMAX * IS];   // routed z (tf32-rounded)
__device__ float d_sZ[(size_t)TMAX * SIW];         // shared z (tf32-rounded)
__device__ float d_xr[(size_t)TMAX * HD];          // tf32-rounded x

// ---------------- helpers ----------------
__device__ __forceinline__ uint32_t smem_u32(const void* p) {
    uint32_t a;
    asm("{ .reg .u64 t; cvta.to.shared.u64 t, %1; cvt.u32.u64 %0, t; }" : "=r"(a) : "l"(p));
    return a;
}
__device__ __forceinline__ unsigned f2tf32(float f) {
    unsigned r;
    asm("cvt.rna.tf32.f32 %0, %1;" : "=r"(r) : "f"(f));
    return r;
}
__device__ __forceinline__ float rndf(float v) {
    return __uint_as_float(f2tf32(v));
}
__device__ __forceinline__ float silu_f(float v) {
    return v / (1.f + expf(-v));
}
#define CPA16(dst, src) \
    asm volatile("cp.async.cg.shared.global [%0], [%1], 16;" :: "r"(dst), "l"(src))
#define CPA_COMMIT() asm volatile("cp.async.commit_group;")
#define CPA_WAIT(n)  asm volatile("cp.async.wait_group %0;" :: "n"(n))

#define LDSM4(r0, r1, r2, r3, addr) \
    asm volatile("ldmatrix.sync.aligned.m8n8.x4.shared.b16 {%0,%1,%2,%3}, [%4];" \
                 : "=r"(r0), "=r"(r1), "=r"(r2), "=r"(r3) : "r"(addr))

__device__ __forceinline__ void mma_tf32(float* d, const unsigned* a, unsigned b0, unsigned b1) {
    asm volatile(
        "mma.sync.aligned.m16n8k8.row.col.f32.tf32.tf32.f32 "
        "{%0,%1,%2,%3}, {%4,%5,%6,%7}, {%8,%9}, {%0,%1,%2,%3};"
        : "+f"(d[0]), "+f"(d[1]), "+f"(d[2]), "+f"(d[3])
        : "r"(a[0]), "r"(a[1]), "r"(a[2]), "r"(a[3]), "r"(b0), "r"(b1));
}

// ---------------- small kernels ----------------
__global__ void zero_cnt_kernel() {
    if (threadIdx.x < NE) d_cnt[threadIdx.x] = 0;
}

// router + fused tf32 pre-rounding of x
__global__ void router_kernel(const float* __restrict__ x,
                              const float* __restrict__ gw,
                              const float* __restrict__ bias) {
    __shared__ float sx[HD];
    __shared__ float sc[NE];
    int t = blockIdx.x;
    const float4* xr = (const float4*)(x + (size_t)t * HD);
    for (int i = threadIdx.x; i < HD / 4; i += blockDim.x)
        ((float4*)sx)[i] = xr[i];
    __syncthreads();

    {
        float4* xo = (float4*)(d_xr + (size_t)t * HD);
        for (int i = threadIdx.x; i < HD / 4; i += blockDim.x) {
            float4 v = ((float4*)sx)[i];
            float4 o;
            o.x = rndf(v.x); o.y = rndf(v.y); o.z = rndf(v.z); o.w = rndf(v.w);
            xo[i] = o;
        }
    }

    int warp = threadIdx.x >> 5, lane = threadIdx.x & 31;
    int nwarp = blockDim.x >> 5;
    for (int e = warp; e < NE; e += nwarp) {
        const float* w = gw + (size_t)e * HD;
        float s = 0.f;
        for (int i = lane; i < HD; i += 32) s = fmaf(sx[i], w[i], s);
        #pragma unroll
        for (int o = 16; o > 0; o >>= 1) s += __shfl_xor_sync(0xffffffffu, s, o);
        if (lane == 0) sc[e] = 1.f / (1.f + expf(-s)) + bias[e];
    }
    __syncthreads();

    if (threadIdx.x == 0) {
        float v[NE];
        #pragma unroll
        for (int e = 0; e < NE; e++) v[e] = sc[e];
        int idx[NK]; float wv[NK]; float sum = 0.f;
        #pragma unroll
        for (int k = 0; k < NK; k++) {
            int bi = 0; float bv = -1e30f;
            #pragma unroll
            for (int e = 0; e < NE; e++) if (v[e] > bv) { bv = v[e]; bi = e; }
            idx[k] = bi; wv[k] = bv; v[bi] = -1e30f; sum += bv;
        }
        float inv = 1.f / (sum + 1e-20f);
        #pragma unroll
        for (int k = 0; k < NK; k++) {
            int e = idx[k];
            int pos = atomicAdd(&d_cnt[e], 1);
            d_tok[e * TMAX + pos] = t;
            d_wgt[e * TMAX + pos] = wv[k] * inv;
        }
    }
}

// ============ fused gate+up+act core (warp 64Mx32z, both g and u) ============
// CTA: 128 M-rows x 128 z-cols. B smem rows [0,128) = Wg rows, [128,256) = Wu.
// Warp (wm,wn): 64 M-rows x 32 z-cols, accumulates accG and accU with identical
// lane mapping -> z = rndf(silu(g)*u*w) in-register.
template<int GATHER>
__device__ __forceinline__ void guz_core(
    const float* __restrict__ A,
    const float* __restrict__ Bg, const float* __restrict__ Bu,
    float* __restrict__ C, const int* __restrict__ tok,
    const float* __restrict__ wgt,
    int M, int K, int N, int by, int bx)
{
    extern __shared__ float smem[];
    uint32_t sbase = smem_u32(smem);

    int tid  = threadIdx.x;
    int lane = tid & 31;
    int warp = tid >> 5;
    int wm   = warp & 1;     // 2 warps along M (64 rows each)
    int wn   = warp >> 1;    // 4 warps along z-cols (32 each)

    int lq = (tid & 7) * 4;
    int lr = tid >> 3;               // 0..31
    const float* aP[4];
    #pragma unroll
    for (int i = 0; i < 4; i++) {
        int r = by * BM + i * 32 + lr;
        int src;
        if (GATHER) src = (r < M) ? tok[r] : tok[0];
        else        src = (r < M) ? r : (M - 1);
        aP[i] = A + (size_t)src * K + lq;
    }
    const float* bPg = Bg + (size_t)(bx * 128 + lr) * K + lq;
    const float* bPu = Bu + (size_t)(bx * 128 + lr) * K + lq;

    uint32_t dOffA = (uint32_t)((lr * LSTR + lq) * 4);
    int      sOffB = SM_A_FLOATS + lr * LSTR + lq;

    uint32_t aAddr[4];
    #pragma unroll
    for (int i = 0; i < 4; i++) {
        int row = wm * 64 + i * 16 + (lane & 15);
        int col = (lane >> 4) << 2;
        aAddr[i] = sbase + (uint32_t)((row * LSTR + col) << 2);
    }
    uint32_t bAddrG[2], bAddrU[2];
    #pragma unroll
    for (int p = 0; p < 2; p++) {
        int nrow = wn * 32 + p * 16 + ((lane >> 4) << 3) + (lane & 7);
        int col  = ((lane >> 3) & 1) << 2;
        bAddrG[p] = sbase + (uint32_t)(SM_A_FLOATS * 4) +
                    (uint32_t)((nrow * LSTR + col) << 2);
        bAddrU[p] = bAddrG[p] + (uint32_t)((128 * LSTR) << 2);
    }

    float accG[4][4][4], accU[4][4][4];
    #pragma unroll
    for (int i = 0; i < 4; i++)
        #pragma unroll
        for (int j = 0; j < 4; j++)
            #pragma unroll
            for (int q = 0; q < 4; q++) { accG[i][j][q] = 0.f; accU[i][j][q] = 0.f; }

    int NT = K / BKT;
    float4 bReg[8];

    auto load_chunkA = [&](int c) {
        uint32_t sb = sbase + (uint32_t)(c & 1) * STAGE_BYTES;
        int k0 = c * BKT;
        #pragma unroll
        for (int i = 0; i < 4; i++)
            CPA16(sb + dOffA + (uint32_t)(i * 32 * LSTR * 4), aP[i] + k0);
        CPA_COMMIT();
    };
    auto ldg_B = [&](int c) {
        int k0 = c * BKT;
        #pragma unroll
        for (int i = 0; i < 4; i++) {
            bReg[i]     = *(const float4*)(bPg + (size_t)i * 32 * K + k0);
            bReg[4 + i] = *(const float4*)(bPu + (size_t)i * 32 * K + k0);
        }
    };
    auto sts_B = [&](int c) {
        float* st = smem + (c & 1) * SM_STAGE + sOffB;
        #pragma unroll
        for (int i = 0; i < 4; i++) {
            float4 v = bReg[i];
            float4 o;
            o.x = rndf(v.x); o.y = rndf(v.y); o.z = rndf(v.z); o.w = rndf(v.w);
            *(float4*)(st + i * 32 * LSTR) = o;
            float4 w = bReg[4 + i];
            float4 p;
            p.x = rndf(w.x); p.y = rndf(w.y); p.z = rndf(w.z); p.w = rndf(w.w);
            *(float4*)(st + (128 + i * 32) * LSTR) = p;
        }
    };

    load_chunkA(0);
    ldg_B(0);
    sts_B(0);

    for (int s = 0; s < NT; s++) {
        CPA_WAIT(0);
        __syncthreads();

        if (s + 1 < NT) {
            ldg_B(s + 1);
            load_chunkA(s + 1);
        }

        uint32_t stOff = (uint32_t)(s & 1) * STAGE_BYTES;

        #pragma unroll
        for (int ks = 0; ks < BKT; ks += 8) {
            uint32_t kOff = stOff + (uint32_t)(ks << 2);
            unsigned a[4][4];
            #pragma unroll
            for (int i = 0; i < 4; i++)
                LDSM4(a[i][0], a[i][1], a[i][2], a[i][3], aAddr[i] + kOff);
            unsigned bg[2][4], bu[2][4];
            #pragma unroll
            for (int p = 0; p < 2; p++) {
                LDSM4(bg[p][0], bg[p][1], bg[p][2], bg[p][3], bAddrG[p] + kOff);
                LDSM4(bu[p][0], bu[p][1], bu[p][2], bu[p][3], bAddrU[p] + kOff);
            }
            #pragma unroll
            for (int j = 0; j < 4; j++) {
                unsigned g0 = bg[j >> 1][(j & 1) * 2];
                unsigned g1 = bg[j >> 1][(j & 1) * 2 + 1];
                #pragma unroll
                for (int i = 0; i < 4; i++)
                    mma_tf32(accG[i][j], a[i], g0, g1);
                unsigned u0 = bu[j >> 1][(j & 1) * 2];
                unsigned u1 = bu[j >> 1][(j & 1) * 2 + 1];
                #pragma unroll
                for (int i = 0; i < 4; i++)
                    mma_tf32(accU[i][j], a[i], u0, u1);
            }
        }

        if (s + 1 < NT) sts_B(s + 1);
    }

    // ---- in-register activation epilogue ----
    #pragma unroll
    for (int i = 0; i < 4; i++) {
        int rl = wm * 64 + i * 16 + (lane >> 2);
        int r0 = by * BM + rl;
        float w0 = 1.f, w1 = 1.f;
        if (GATHER) {
            if (r0 < M)     w0 = wgt[r0];
            if (r0 + 8 < M) w1 = wgt[r0 + 8];
        }
        #pragma unroll
        for (int j = 0; j < 4; j++) {
            int c0 = bx * 128 + wn * 32 + j * 8 + 2 * (lane & 3);
            if (r0 < M) {
                float2 z;
                z.x = rndf(silu_f(accG[i][j][0]) * accU[i][j][0] * w0);
                z.y = rndf(silu_f(accG[i][j][1]) * accU[i][j][1] * w0);
                *(float2*)(C + (size_t)r0 * N + c0) = z;
            }
            if (r0 + 8 < M) {
                float2 z;
                z.x = rndf(silu_f(accG[i][j][2]) * accU[i][j][2] * w1);
                z.y = rndf(silu_f(accG[i][j][3]) * accU[i][j][3] * w1);
                *(float2*)(C + (size_t)(r0 + 8) * N + c0) = z;
            }
        }
    }
}

__global__ __launch_bounds__(256, 1)
void gemm_guz(const float* __restrict__ Wg, const float* __restrict__ Wu,
              const float* __restrict__ Sg, const float* __restrict__ Su,
              int Tn) {
    int e  = blockIdx.z;
    int bx = blockIdx.x;
    int by = blockIdx.y;

    if (e < NE) {
        int M = d_cnt[e];
        if (by * BM >= M) return;
        guz_core<1>(d_xr, Wg + (size_t)e * IS * HD, Wu + (size_t)e * IS * HD,
                    d_bufZ + (size_t)e * TMAX * IS,
                    d_tok + e * TMAX, d_wgt + e * TMAX, M, HD, IS, by, bx);
    } else {
        if (by * BM >= Tn) return;
        guz_core<0>(d_xr, Sg, Su, d_sZ, nullptr, nullptr, Tn, HD, SIW, by, bx);
    }
}

// ============ down GEMM core (warp 64x64) ============
// CTA: 128 M-rows x 256 N-cols.
template<int ATOMIC, int SCAT>
__device__ __forceinline__ void gemm_core(
    const float* __restrict__ A, const float* __restrict__ B,
    float* __restrict__ C, const int* __restrict__ tok,
    int M, int K, int N, int by, int bx)
{
    extern __shared__ float smem[];
    uint32_t sbase = smem_u32(smem);

    int tid  = threadIdx.x;
    int lane = tid & 31;
    int warp = tid >> 5;
    int wm   = warp & 1;
    int wn   = warp >> 1;    // 4 warps x 64 N-cols

    int lq = (tid & 7) * 4;
    int lr = tid >> 3;               // 0..31
    const float* aP[4];
    #pragma unroll
    for (int i = 0; i < 4; i++) {
        int r = by * BM + i * 32 + lr;
        int src = (r < M) ? r : (M - 1);
        aP[i] = A + (size_t)src * K + lq;
    }
    const float* bP0 = B + (size_t)(bx * BNR + lr) * K + lq;

    uint32_t dOffA = (uint32_t)((lr * LSTR + lq) * 4);
    int      sOffB = SM_A_FLOATS + lr * LSTR + lq;

    uint32_t aAddr[4];
    #pragma unroll
    for (int i = 0; i < 4; i++) {
        int row = wm * 64 + i * 16 + (lane & 15);
        int col = (lane >> 4) << 2;
        aAddr[i] = sbase + (uint32_t)((row * LSTR + col) << 2);
    }
    uint32_t bAddr[4];
    #pragma unroll
    for (int p = 0; p < 4; p++) {
        int nrow = wn * 64 + p * 16 + ((lane >> 4) << 3) + (lane & 7);
        int col  = ((lane >> 3) & 1) << 2;
        bAddr[p] = sbase + (uint32_t)(SM_A_FLOATS * 4) +
                   (uint32_t)((nrow * LSTR + col) << 2);
    }

    float acc[4][8][4];
    #pragma unroll
    for (int i = 0; i < 4; i++)
        #pragma unroll
        for (int j = 0; j < 8; j++)
            #pragma unroll
            for (int q = 0; q < 4; q++) acc[i][j][q] = 0.f;

    int NT = K / BKT;
    float4 bReg[8];

    auto load_chunkA = [&](int c) {
        uint32_t sb = sbase + (uint32_t)(c & 1) * STAGE_BYTES;
        int k0 = c * BKT;
        #pragma unroll
        for (int i = 0; i < 4; i++)
            CPA16(sb + dOffA + (uint32_t)(i * 32 * LSTR * 4), aP[i] + k0);
        CPA_COMMIT();
    };
    auto ldg_B = [&](int c) {
        int k0 = c * BKT;
        #pragma unroll
        for (int i = 0; i < 8; i++)
            bReg[i] = *(const float4*)(bP0 + (size_t)i * 32 * K + k0);
    };
    auto sts_B = [&](int c) {
        float* st = smem + (c & 1) * SM_STAGE + sOffB;
        #pragma unroll
        for (int i = 0; i < 8; i++) {
            float4 v = bReg[i];
            float4 o;
            o.x = rndf(v.x); o.y = rndf(v.y); o.z = rndf(v.z); o.w = rndf(v.w);
            *(float4*)(st + i * 32 * LSTR) = o;
        }
    };

    load_chunkA(0);
    ldg_B(0);
    sts_B(0);

    for (int s = 0; s < NT; s++) {
        CPA_WAIT(0);
        __syncthreads();

        if (s + 1 < NT) {
            ldg_B(s + 1);
            load_chunkA(s + 1);
        }

        uint32_t stOff = (uint32_t)(s & 1) * STAGE_BYTES;

        #pragma unroll
        for (int ks = 0; ks < BKT; ks += 8) {
            uint32_t kOff = stOff + (uint32_t)(ks << 2);
            unsigned a[4][4];
            #pragma unroll
            for (int i = 0; i < 4; i++)
                LDSM4(a[i][0], a[i][1], a[i][2], a[i][3], aAddr[i] + kOff);
            unsigned b[4][4];
            #pragma unroll
            for (int p = 0; p < 4; p++)
                LDSM4(b[p][0], b[p][1], b[p][2], b[p][3], bAddr[p] + kOff);
            #pragma unroll
            for (int j = 0; j < 8; j++) {
                unsigned b0 = b[j >> 1][(j & 1) * 2];
                unsigned b1 = b[j >> 1][(j & 1) * 2 + 1];
                #pragma unroll
                for (int i = 0; i < 4; i++)
                    mma_tf32(acc[i][j], a[i], b0, b1);
            }
        }

        if (s + 1 < NT) sts_B(s + 1);
    }

    #pragma unroll
    for (int i = 0; i < 4; i++) {
        int r0 = by * BM + wm * 64 + i * 16 + (lane >> 2);
        #pragma unroll
        for (int j = 0; j < 8; j++) {
            int c0 = bx * BNR + wn * 64 + j * 8 + 2 * (lane & 3);
            if (ATOMIC) {
                if (r0 < M) {
                    int tr = SCAT ? tok[r0] : r0;
                    atomicAdd(C + (size_t)tr * N + c0,     acc[i][j][0]);
                    atomicAdd(C + (size_t)tr * N + c0 + 1, acc[i][j][1]);
                }
                if (r0 + 8 < M) {
                    int tr = SCAT ? tok[r0 + 8] : (r0 + 8);
                    atomicAdd(C + (size_t)tr * N + c0,     acc[i][j][2]);
                    atomicAdd(C + (size_t)tr * N + c0 + 1, acc[i][j][3]);
                }
            } else {
                if (r0 < M) {
                    *(float2*)(C + (size_t)r0 * N + c0) =
                        make_float2(acc[i][j][0], acc[i][j][1]);
                }
                if (r0 + 8 < M) {
                    *(float2*)(C + (size_t)(r0 + 8) * N + c0) =
                        make_float2(acc[i][j][2], acc[i][j][3]);
                }
            }
        }
    }
}

// shared-expert down: direct stores to out
__global__ __launch_bounds__(256, 1)
void gemm_sd(const float* __restrict__ Sd, float* __restrict__ out, int Tn) {
    if ((int)blockIdx.y * BM >= Tn) return;
    gemm_core<0, 0>(d_sZ, Sd, out, nullptr, Tn, SIW, HD, blockIdx.y, blockIdx.x);
}

// routed down: scatter-atomicAdd into out
__global__ __launch_bounds__(256, 1)
void gemm_rd(const float* __restrict__ Wd, float* __restrict__ out) {
    int e = blockIdx.z;
    int M = d_cnt[e];
    if ((int)blockIdx.y * BM >= M) return;
    gemm_core<1, 1>(d_bufZ + (size_t)e * TMAX * IS,
                    Wd + (size_t)e * HD * IS,
                    out, d_tok + e * TMAX, M, IS, HD, blockIdx.y, blockIdx.x);
}

// ---------------- launch ----------------
extern "C" void kernel_launch(void* const* d_in, const int* in_sizes, int n_in,
                              void* d_out, int out_size) {
    const float* x    = (const float*)d_in[0];
    const float* gw   = (const float*)d_in[1];
    const float* bias = (const float*)d_in[2];
    const float* Wg   = (const float*)d_in[3];
    const float* Wu   = (const float*)d_in[4];
    const float* Wd   = (const float*)d_in[5];
    const float* Sg   = (const float*)d_in[6];
    const float* Su   = (const float*)d_in[7];
    const float* Sd   = (const float*)d_in[8];
    float* out = (float*)d_out;

    int Tn = in_sizes[0] / HD;            // 4096 tokens
    int mt = (Tn + BM - 1) / BM;          // 32

    static int smem_set = 0;
    if (!smem_set) {
        cudaFuncSetAttribute(gemm_guz, cudaFuncAttributeMaxDynamicSharedMemorySize, DSMEM_BYTES);
        cudaFuncSetAttribute(gemm_sd,  cudaFuncAttributeMaxDynamicSharedMemorySize, DSMEM_BYTES);
        cudaFuncSetAttribute(gemm_rd,  cudaFuncAttributeMaxDynamicSharedMemorySize, DSMEM_BYTES);
        smem_set = 1;
    }

    zero_cnt_kernel<<<1, 32>>>();
    router_kernel<<<Tn, 128>>>(x, gw, bias);   // also writes tf32-rounded d_xr

    // fused gate+up+activation: 16 routed experts + shared, one launch
    // (128 z-cols per CTA -> bx = IS/128 = 16)
    gemm_guz<<<dim3(IS / 128, 32, NE + 1), 256, DSMEM_BYTES>>>(Wg, Wu, Sg, Su, Tn);

    // shared down (direct store) then routed down (atomicAdd) — stream-ordered
    gemm_sd<<<dim3(HD / BNR, mt, 1), 256, DSMEM_BYTES>>>(Sd, out, Tn);
    gemm_rd<<<dim3(HD / BNR, 32, NE), 256, DSMEM_BYTES>>>(Wd, out);

    (void)n_in; (void)out_size;
}